// round 15
// baseline (speedup 1.0000x reference)
#include <cuda_runtime.h>
#include <math.h>

#define NG   512
#define IMGW 224
#define VPIX (IMGW*IMGW)
#define NPIX (3*VPIX)

#define L2E   1.4426950408889634f
#define UMIN  (-28.853900817779268f)       // -20 * log2(e)
#define EKF   2.061153622438558e-9f        // exp(-20)

// Scratch (no cudaMalloc allowed)
__device__ float  g_par[3*NG*8];   // px,py,A,B,C,w0,F0,rsat2  (A=-a*l2e etc.)
__device__ float  g_d[NPIX];       // splat output
__device__ float  g_t[NPIX];       // fill output (pre-norm)
__device__ double g_acc[2];        // sum, sumsq

__device__ __forceinline__ float ex2f(float x)
{
    float y;
    asm("ex2.approx.f32 %0, %1;" : "=f"(y) : "f"(x));
    return y;
}

// ---------------------------------------------------------------------------
// prep: 48 blocks x 32 threads, thread -> (view, gaussian).  (same as R14)
// ---------------------------------------------------------------------------
__global__ __launch_bounds__(32) void prep_kernel(const float* __restrict__ pos,
                                                  const float* __restrict__ cov,
                                                  const float* __restrict__ opa,
                                                  const float* __restrict__ imp)
{
    const int lane = threadIdx.x;
    const int bx   = blockIdx.x;          // [0,48)
    const int v    = bx >> 4;
    const int n    = (bx & 15) * 32 + lane;

    if (bx == 0 && lane == 0) { g_acc[0] = 0.0; g_acc[1] = 0.0; }

    // global min/max of each coordinate (warp-redundant)
    float mn0 =  1e30f, mn1 =  1e30f, mn2 =  1e30f;
    float mx0 = -1e30f, mx1 = -1e30f, mx2 = -1e30f;
    for (int g = lane; g < NG; g += 32) {
        float p0 = pos[g*3+0], p1 = pos[g*3+1], p2 = pos[g*3+2];
        mn0 = fminf(mn0, p0); mx0 = fmaxf(mx0, p0);
        mn1 = fminf(mn1, p1); mx1 = fmaxf(mx1, p1);
        mn2 = fminf(mn2, p2); mx2 = fmaxf(mx2, p2);
    }
    #pragma unroll
    for (int o = 16; o > 0; o >>= 1) {
        mn0 = fminf(mn0, __shfl_xor_sync(0xffffffffu, mn0, o));
        mx0 = fmaxf(mx0, __shfl_xor_sync(0xffffffffu, mx0, o));
        mn1 = fminf(mn1, __shfl_xor_sync(0xffffffffu, mn1, o));
        mx1 = fmaxf(mx1, __shfl_xor_sync(0xffffffffu, mx1, o));
        mn2 = fminf(mn2, __shfl_xor_sync(0xffffffffu, mn2, o));
        mx2 = fmaxf(mx2, __shfl_xor_sync(0xffffffffu, mx2, o));
    }
    float bmn[3] = { mn0, mn1, mn2 };
    float bmx[3] = { mx0, mx1, mx2 };

    // cov chain applied (v+1) times (fp32, reference op order; reciprocal-mul)
    float C00 = cov[n*9+0], C01 = cov[n*9+1], C02 = cov[n*9+2];
    float C10 = cov[n*9+3], C11 = cov[n*9+4], C12 = cov[n*9+5];
    float C20 = cov[n*9+6], C21 = cov[n*9+7], C22 = cov[n*9+8];
    for (int it = 0; it <= v; it++) {
        float t;
        t = 0.5f*(C01 + C10); C01 = t; C10 = t;
        t = 0.5f*(C02 + C20); C02 = t; C20 = t;
        t = 0.5f*(C12 + C21); C12 = t; C21 = t;
        C00 += 1e-6f; C11 += 1e-6f; C22 += 1e-6f;
        float nrm = sqrtf(C00*C00 + C01*C01 + C02*C02 +
                          C10*C10 + C11*C11 + C12*C12 +
                          C20*C20 + C21*C21 + C22*C22);
        float rden = 1.0f / (nrm + 1e-6f);
        C00 *= rden; C01 *= rden; C02 *= rden;
        C10 *= rden; C11 *= rden; C12 *= rden;
        C20 *= rden; C21 *= rden; C22 *= rden;
    }

    // f64 symmetric 3x3 inverse
    double d00 = C00, d01 = C01, d02 = C02, d11 = C11, d12 = C12, d22 = C22;
    double m00 = d11*d22 - d12*d12;
    double m01 = d02*d12 - d01*d22;
    double m02 = d01*d12 - d02*d11;
    double m11 = d00*d22 - d02*d02;
    double m12 = d01*d02 - d00*d12;
    double m22 = d00*d11 - d01*d01;
    double det = d00*m00 + d01*m01 + d02*m02;
    double idet = 1.0 / det;

    const int A0[3] = {0, 0, 2};
    const int A1[3] = {1, 2, 1};
    const int a0 = A0[v], a1 = A1[v];
    double cof[3][3] = {{m00,m01,m02},{m01,m11,m12},{m02,m12,m22}};
    float a  = (float)(cof[a0][a0]*idet) + 1e-10f;
    float b2 = 2.0f * (float)(cof[a0][a1]*idet);
    float c  = (float)(cof[a1][a1]*idet) + 1e-10f;

    // affine map to [0,111] screen coords (replicating reference fp ops)
    float mnx = bmn[a0], mxx = bmx[a0];
    float mny = bmn[a1], mxy = bmx[a1];
    float rx  = (mxx - mnx) + 1e-6f;
    float m2x = mnx - 0.5f*rx;
    float x2x = mxx + 0.5f*rx;
    float r2x = (x2x - m2x) + 1e-6f;
    float ry  = (mxy - mny) + 1e-6f;
    float m2y = mny - 0.5f*ry;
    float x2y = mxy + 0.5f*ry;
    float r2y = (x2y - m2y) + 1e-6f;
    float Pa  = pos[n*3 + a0];
    float Pb  = pos[n*3 + a1];
    float px = fminf(fmaxf((Pa - m2x) / r2x * 111.0f, 0.0f), 111.0f);
    float py = fminf(fmaxf((Pb - m2y) / r2y * 111.0f, 0.0f), 111.0f);

    float w0 = opa[n] * fminf(fmaxf(imp[n], 0.5f), 2.0f);

    float Af = -L2E * a;
    float Bf = -L2E * b2;
    float Cf = -L2E * c;
    float F0 = 0.1875f * (Af + Cf);

    float bh  = 0.5f * b2;
    float lam = 0.5f*(a + c) - sqrtf(0.25f*(a - c)*(a - c) + bh*bh);
    float rsat2;
    if (lam > 1e-8f) {
        float rs = sqrtf(20.0f / lam) + 0.3536f;
        rsat2 = rs * rs;
    } else {
        rsat2 = 3.0e38f;
    }

    float* dst = &g_par[(v*NG + n)*8];
    dst[0] = px; dst[1] = py; dst[2] = Af; dst[3] = Bf;
    dst[4] = Cf; dst[5] = w0; dst[6] = F0; dst[7] = rsat2;
}

// ---------------------------------------------------------------------------
// Exact-eval inner loop: 4 pixels per thread (rows y, y+8, y+16, y+24).
// One q0/q1 load pair + dx/bdx/base amortized over 4 evals.
// ---------------------------------------------------------------------------
template<bool EDGE, bool MASKED>
__device__ __forceinline__ void eval_list4(
    const float* __restrict__ sp, int i0, int i1,
    float sx, float vx,
    const float* sy, const float* vy,
    float hx, const float* hy,
    float* S, float* mx, float* mn, bool& skipped)
{
    #pragma unroll 2
    for (int i = i0; i < i1; i++) {
        float4 q0 = *(const float4*)(sp + i*8);      // px,py,A,B
        float4 q1 = *(const float4*)(sp + i*8 + 4);  // C,w0,F0,rsat2
        bool m[4] = { true, true, true, true };
        if (MASKED) {
            float dxh  = hx - q0.x;
            float dxh2 = dxh * dxh;
            bool anym = false;
            #pragma unroll
            for (int j = 0; j < 4; j++) {
                float dyh = hy[j] - q0.y;
                m[j] = fmaf(dyh, dyh, dxh2) < 400.0f;
                anym |= m[j];
            }
            if (!__any_sync(0xffffffffu, anym)) { skipped = true; continue; }
        }
        float dx  = sx - q0.x;
        float bdx = q0.w * dx;
        float base;
        if (EDGE) base = q0.z * fmaf(dx, dx, vx);
        else      base = fmaf(q0.z, dx*dx, q1.z);
        #pragma unroll
        for (int j = 0; j < 4; j++) {
            float dy = sy[j] - q0.y;
            float u;
            if (EDGE) u = fmaf(q1.x, fmaf(dy, dy, vy[j]), fmaf(bdx, dy, base));
            else      u = fmaf(q1.x, dy*dy, fmaf(bdx, dy, base));
            u = fmaxf(fminf(u, 0.0f), UMIN);
            float w = m[j] ? q1.y * ex2f(u) : 0.0f;
            S[j] += w; mx[j] = fmaxf(mx[j], w); mn[j] = fminf(mn[j], w);
        }
    }
}

// ---------------------------------------------------------------------------
// Splat: 16x32 pixel tile, 128 threads, 4 pixels/thread (rows y,y+8,y+16,y+24).
// Compaction classes (per tile): fullA / partA / B (saturated+inside, scalar)
// / C (saturated boundary, disc test only) / culled.
// ---------------------------------------------------------------------------
__global__ __launch_bounds__(128) void splat_kernel()
{
    const int v    = blockIdx.y;
    const int tile = (blockIdx.x * 15) % 98;     // wave-balance permutation
    const int fx0  = (tile % 14) * 16, fy0 = (tile / 14) * 32;
    const int t    = threadIdx.x;
    const int lane = t & 31, wid = t >> 5;
    const int fx   = fx0 + (t & 15);
    const int r    = t >> 4;                     // 0..7

    float sx, vx;
    if (fx == 0)        { sx = 0.0f;   vx = 0.0f; }
    else if (fx == 223) { sx = 111.0f; vx = 0.0f; }
    else                { sx = (float)fx * 0.5f - 0.25f; vx = 0.1875f; }

    float sy[4], vy[4], hy[4];
    int   fy[4];
    #pragma unroll
    for (int j = 0; j < 4; j++) {
        int f = fy0 + r + 8*j;
        fy[j] = f;
        hy[j] = (float)(f >> 1);
        if (f == 0)        { sy[j] = 0.0f;   vy[j] = 0.0f; }
        else if (f == 223) { sy[j] = 111.0f; vy[j] = 0.0f; }
        else               { sy[j] = (float)f * 0.5f - 0.25f; vy[j] = 0.1875f; }
    }

    const float hx = (float)(fx >> 1);

    const float rx0 = (float)(fx0 >> 1), rx1 = (float)((fx0 + 15) >> 1);
    const float ry0 = (float)(fy0 >> 1), ry1 = (float)((fy0 + 31) >> 1);

    __shared__ float spA[NG * 8];
    __shared__ float spC[NG * 4];
    __shared__ int   cFA[4], cPA[4], cC[4], cB[4];
    __shared__ float rSum[4], rMin[4], rMax[4];
    __shared__ int   s_front, s_back, s_c, s_nB;
    __shared__ float s_sumB, s_minB, s_maxB;
    if (t == 0) {
        s_front = 0; s_back = NG; s_c = 0; s_nB = 0;
        s_sumB = 0.0f; s_minB = 1e30f; s_maxB = -1e30f;
    }
    __syncthreads();

    const float* par = g_par + v * NG * 8;
    const unsigned ltm = (1u << lane) - 1u;

    for (int base = 0; base < NG; base += 128) {
        const int n = base + t;
        float4 q0 = *(const float4*)(par + n*8);
        float4 q1 = *(const float4*)(par + n*8 + 4);
        float px = q0.x, py = q0.y;
        float nx = fminf(fmaxf(px, rx0), rx1) - px;
        float ny = fminf(fmaxf(py, ry0), ry1) - py;
        float dnear2 = nx*nx + ny*ny;
        float fxd = fmaxf(px - rx0, rx1 - px);
        float fyd = fmaxf(py - ry0, ry1 - py);
        float dfar2 = fxd*fxd + fyd*fyd;

        bool keep   = dnear2 < 400.0f;
        bool inside = dfar2  < 400.0f;
        bool sat    = keep && (dnear2 >= q1.w);
        bool bBall  = sat && inside;
        bool bCc    = sat && !inside;
        bool bFA    = keep && !sat && inside;
        bool bPA    = keep && !sat && !inside;

        unsigned mFA = __ballot_sync(0xffffffffu, bFA);
        unsigned mPA = __ballot_sync(0xffffffffu, bPA);
        unsigned mCc = __ballot_sync(0xffffffffu, bCc);
        unsigned mBB = __ballot_sync(0xffffffffu, bBall);

        // warp-reduce B scalars
        float sv  = bBall ? q1.y : 0.0f;
        float mnv = bBall ? q1.y : 1e30f;
        float mxv = bBall ? q1.y : -1e30f;
        #pragma unroll
        for (int o = 16; o > 0; o >>= 1) {
            sv  += __shfl_xor_sync(0xffffffffu, sv,  o);
            mnv  = fminf(mnv, __shfl_xor_sync(0xffffffffu, mnv, o));
            mxv  = fmaxf(mxv, __shfl_xor_sync(0xffffffffu, mxv, o));
        }
        if (lane == 0) {
            cFA[wid] = __popc(mFA); cPA[wid] = __popc(mPA);
            cC[wid]  = __popc(mCc); cB[wid]  = __popc(mBB);
            rSum[wid] = sv; rMin[wid] = mnv; rMax[wid] = mxv;
        }
        __syncthreads();

        int offF = s_front, offP = 0, offC = s_c;
        int totF = 0, totP = 0;
        #pragma unroll
        for (int w = 0; w < 4; w++) {
            if (w < wid) { offF += cFA[w]; offP += cPA[w]; offC += cC[w]; }
            totF += cFA[w]; totP += cPA[w];
        }
        int basePslot = s_back - totP;
        if (bFA | bPA) {
            int slot = bFA ? (offF + __popc(mFA & ltm))
                           : (basePslot + offP + __popc(mPA & ltm));
            *(float4*)(spA + slot*8)     = q0;
            *(float4*)(spA + slot*8 + 4) = q1;
        }
        if (bCc) {
            int slot = offC + __popc(mCc & ltm);
            *(float4*)(spC + slot*4) = make_float4(px, py, EKF * q1.y, 0.0f);
        }
        __syncthreads();
        if (t == 0) {
            int tF = 0, tP = 0, tC = 0, tB = 0;
            float aS = 0.0f, aMn = 1e30f, aMx = -1e30f;
            #pragma unroll
            for (int w = 0; w < 4; w++) {
                tF += cFA[w]; tP += cPA[w]; tC += cC[w]; tB += cB[w];
                aS += rSum[w]; aMn = fminf(aMn, rMin[w]); aMx = fmaxf(aMx, rMax[w]);
            }
            s_front += tF; s_back -= tP; s_c += tC; s_nB += tB;
            s_sumB += aS;
            s_minB = fminf(s_minB, aMn);
            s_maxB = fmaxf(s_maxB, aMx);
        }
        __syncthreads();
    }
    const int nfull = s_front, pstart = s_back, nC = s_c, nB = s_nB;
    const float sumB = s_sumB, minB = s_minB, maxB = s_maxB;

    float S[4]  = { 0.0f, 0.0f, 0.0f, 0.0f };
    float mx[4] = { -1e30f, -1e30f, -1e30f, -1e30f };
    float mn[4] = {  1e30f,  1e30f,  1e30f,  1e30f };
    bool skipped = false;

    const bool interior = (fx0 != 0) && (fx0 != 208) && (fy0 != 0) && (fy0 != 192);
    if (interior) {
        eval_list4<false,false>(spA, 0, nfull, sx, vx, sy, vy, hx, hy,
                                S, mx, mn, skipped);
        eval_list4<false,true >(spA, pstart, NG, sx, vx, sy, vy, hx, hy,
                                S, mx, mn, skipped);
    } else {
        eval_list4<true,false>(spA, 0, nfull, sx, vx, sy, vy, hx, hy,
                               S, mx, mn, skipped);
        eval_list4<true,true >(spA, pstart, NG, sx, vx, sy, vy, hx, hy,
                               S, mx, mn, skipped);
    }

    // C list: saturated, disc-boundary -> per-pixel disc test only
    #pragma unroll 2
    for (int i = 0; i < nC; i++) {
        float4 q = *(const float4*)(spC + i*4);   // px,py,EKF*w0
        float dxh  = hx - q.x;
        float dxh2 = dxh * dxh;
        #pragma unroll
        for (int j = 0; j < 4; j++) {
            float dyh = hy[j] - q.y;
            float w = (fmaf(dyh, dyh, dxh2) < 400.0f) ? q.z : 0.0f;
            S[j] += w; mx[j] = fmaxf(mx[j], w); mn[j] = fminf(mn[j], w);
        }
    }

    // B scalars: identical contribution to every tile pixel
    if (nB > 0) {
        float add = EKF * sumB;
        float bmnv = EKF * minB, bmxv = EKF * maxB;
        #pragma unroll
        for (int j = 0; j < 4; j++) {
            S[j] += add;
            mn[j] = fminf(mn[j], bmnv); mx[j] = fmaxf(mx[j], bmxv);
        }
    }

    // culled / skipped gaussians contribute exactly zero
    int listed = nfull + (NG - pstart) + nC + nB;
    if (skipped || listed < NG) {
        #pragma unroll
        for (int j = 0; j < 4; j++) {
            mn[j] = fminf(mn[j], 0.0f); mx[j] = fmaxf(mx[j], 0.0f);
        }
    }

    #pragma unroll
    for (int j = 0; j < 4; j++) {
        float dm = 0.5f*(S[j] - 512.0f*mn[j])/((mx[j] - mn[j]) + 1e-6f)
                 + S[j]/(S[j] + 1e-6f);
        g_d[v*VPIX + fy[j]*IMGW + fx] = dm;
    }
}

// ---------------------------------------------------------------------------
// Fully fused fill (both steps) + stats.  (same as R14)
// ---------------------------------------------------------------------------
__device__ __forceinline__ void blur_weights(float& K0, float& K1, float& K2, float& K3)
{
    const double E1 = 0.60653065971263342;
    const double E2 = 0.13533528323661270;
    const double E3 = 0.011108996538242306;
    const double KS = 1.0 + 2.0*(E1 + E2 + E3);
    K0 = (float)(1.0/KS); K1 = (float)(E1/KS); K2 = (float)(E2/KS); K3 = (float)(E3/KS);
}

__global__ __launch_bounds__(256) void fill2_kernel()
{
    const int v  = blockIdx.y;
    const int r0 = blockIdx.x * 8;
    const int t  = threadIdx.x;

    float K0,K1,K2,K3; blur_weights(K0,K1,K2,K3);

    __shared__ float sA[20 * 224];
    __shared__ float sB[14 * 224];
    __shared__ float sC[14 * 224];

    for (int idx = t; idx < 20*224; idx += 256) {
        int row = idx / 224;
        int x   = idx - row * 224;
        int y   = r0 - 6 + row;
        sA[idx] = (y >= 0 && y < 224) ? g_d[v*VPIX + y*224 + x] : 0.0f;
    }
    __syncthreads();

    for (int idx = t; idx < 14*224; idx += 256) {
        sB[idx] = K0 *  sA[idx + 3*224]
                + K1 * (sA[idx + 2*224] + sA[idx + 4*224])
                + K2 * (sA[idx + 1*224] + sA[idx + 5*224])
                + K3 * (sA[idx]          + sA[idx + 6*224]);
    }
    __syncthreads();

    for (int idx = t; idx < 14*224; idx += 256) {
        int j = idx / 224;
        int x = idx - j * 224;
        int yabs = r0 - 3 + j;
        float acc = K0 * sB[idx];
        if (x >= 1)   acc += K1 * sB[idx - 1];
        if (x >= 2)   acc += K2 * sB[idx - 2];
        if (x >= 3)   acc += K3 * sB[idx - 3];
        if (x <= 222) acc += K1 * sB[idx + 1];
        if (x <= 221) acc += K2 * sB[idx + 2];
        if (x <= 220) acc += K3 * sB[idx + 3];
        float dv = sA[idx + 3*224];
        float res = (dv > 1e-6f) ? dv : acc;
        sC[idx] = (yabs >= 0 && yabs < 224) ? res : 0.0f;
    }
    __syncthreads();

    for (int idx = t; idx < 8*224; idx += 256) {
        sB[idx] = K0 *  sC[idx + 3*224]
                + K1 * (sC[idx + 2*224] + sC[idx + 4*224])
                + K2 * (sC[idx + 1*224] + sC[idx + 5*224])
                + K3 * (sC[idx]          + sC[idx + 6*224]);
    }
    __syncthreads();

    double s1 = 0.0, s2 = 0.0;
    for (int idx = t; idx < 8*224; idx += 256) {
        int j = idx / 224;
        int x = idx - j * 224;
        float acc = K0 * sB[idx];
        if (x >= 1)   acc += K1 * sB[idx - 1];
        if (x >= 2)   acc += K2 * sB[idx - 2];
        if (x >= 3)   acc += K3 * sB[idx - 3];
        if (x <= 222) acc += K1 * sB[idx + 1];
        if (x <= 221) acc += K2 * sB[idx + 2];
        if (x <= 220) acc += K3 * sB[idx + 3];
        float dv  = sC[idx + 3*224];
        float res = (dv > 1e-6f) ? dv : acc;
        g_t[v*VPIX + (r0 + j)*224 + x] = res;
        s1 += (double)res; s2 += (double)res * (double)res;
    }

    #pragma unroll
    for (int o = 16; o > 0; o >>= 1) {
        s1 += __shfl_down_sync(0xffffffffu, s1, o);
        s2 += __shfl_down_sync(0xffffffffu, s2, o);
    }
    __shared__ double ws[8], ws2[8];
    int lane = t & 31, wid = t >> 5;
    if (lane == 0) { ws[wid] = s1; ws2[wid] = s2; }
    __syncthreads();
    if (t == 0) {
        double a = 0.0, b = 0.0;
        for (int w = 0; w < 8; w++) { a += ws[w]; b += ws2[w]; }
        atomicAdd(&g_acc[0], a);
        atomicAdd(&g_acc[1], b);
    }
}

// ---------------------------------------------------------------------------
// Normalize: f64 mean/std once per block; float4 vectorized stream.
// NPIX = 150528 = 147 * 256 * 4 exactly.
// ---------------------------------------------------------------------------
__global__ __launch_bounds__(256) void norm_kernel(float* __restrict__ out)
{
    __shared__ float sBias, sScale;
    if (threadIdx.x == 0) {
        double s1 = g_acc[0], s2 = g_acc[1];
        double mean = s1 / (double)NPIX;
        double var  = (s2 - s1*mean) / (double)(NPIX - 1);
        double stdd = sqrt(fmax(var, 0.0));
        sBias  = (float)mean;
        sScale = (float)(1.0 / (stdd + 1e-6));
    }
    __syncthreads();
    int i = blockIdx.x*256 + threadIdx.x;
    float4 x = ((const float4*)g_t)[i];
    float b = sBias, s = sScale;
    float4 y;
    y.x = (x.x - b) * s;
    y.y = (x.y - b) * s;
    y.z = (x.z - b) * s;
    y.w = (x.w - b) * s;
    ((float4*)out)[i] = y;
}

// ---------------------------------------------------------------------------
extern "C" void kernel_launch(void* const* d_in, const int* in_sizes, int n_in,
                              void* d_out, int out_size)
{
    const float* pos = (const float*)d_in[0];  // (1,512,3)
    const float* cov = (const float*)d_in[1];  // (1,512,3,3)
    const float* opa = (const float*)d_in[2];  // (1,512)
    const float* imp = (const float*)d_in[3];  // (1,1000)

    prep_kernel<<<48, 32>>>(pos, cov, opa, imp);
    splat_kernel<<<dim3(98, 3), 128>>>();
    fill2_kernel<<<dim3(28, 3), 256>>>();
    norm_kernel<<<NPIX/1024, 256>>>((float*)d_out);
}

// round 16
// speedup vs baseline: 1.5578x; 1.5578x over previous
#include <cuda_runtime.h>
#include <math.h>

#define NG   512
#define IMGW 224
#define VPIX (IMGW*IMGW)
#define NPIX (3*VPIX)

#define L2E   1.4426950408889634f
#define UMIN  (-28.853900817779268f)       // -20 * log2(e)
#define EKF   2.061153622438558e-9f        // exp(-20)

// Scratch (no cudaMalloc allowed)
__device__ float  g_par[3*NG*8];   // px,py,A,B,C,w0,F0,rsat2  (A=-a*l2e etc.)
__device__ float  g_d[NPIX];       // splat output
__device__ float  g_t[NPIX];       // fill output (pre-norm)
__device__ double g_acc[2];        // sum, sumsq

__device__ __forceinline__ float ex2f(float x)
{
    float y;
    asm("ex2.approx.f32 %0, %1;" : "=f"(y) : "f"(x));
    return y;
}

// ---------------------------------------------------------------------------
// prep: 48 blocks x 32 threads, thread -> (view, gaussian).  (same as R14)
// ---------------------------------------------------------------------------
__global__ __launch_bounds__(32) void prep_kernel(const float* __restrict__ pos,
                                                  const float* __restrict__ cov,
                                                  const float* __restrict__ opa,
                                                  const float* __restrict__ imp)
{
    const int lane = threadIdx.x;
    const int bx   = blockIdx.x;          // [0,48)
    const int v    = bx >> 4;
    const int n    = (bx & 15) * 32 + lane;

    if (bx == 0 && lane == 0) { g_acc[0] = 0.0; g_acc[1] = 0.0; }

    // global min/max of each coordinate (warp-redundant)
    float mn0 =  1e30f, mn1 =  1e30f, mn2 =  1e30f;
    float mx0 = -1e30f, mx1 = -1e30f, mx2 = -1e30f;
    for (int g = lane; g < NG; g += 32) {
        float p0 = pos[g*3+0], p1 = pos[g*3+1], p2 = pos[g*3+2];
        mn0 = fminf(mn0, p0); mx0 = fmaxf(mx0, p0);
        mn1 = fminf(mn1, p1); mx1 = fmaxf(mx1, p1);
        mn2 = fminf(mn2, p2); mx2 = fmaxf(mx2, p2);
    }
    #pragma unroll
    for (int o = 16; o > 0; o >>= 1) {
        mn0 = fminf(mn0, __shfl_xor_sync(0xffffffffu, mn0, o));
        mx0 = fmaxf(mx0, __shfl_xor_sync(0xffffffffu, mx0, o));
        mn1 = fminf(mn1, __shfl_xor_sync(0xffffffffu, mn1, o));
        mx1 = fmaxf(mx1, __shfl_xor_sync(0xffffffffu, mx1, o));
        mn2 = fminf(mn2, __shfl_xor_sync(0xffffffffu, mn2, o));
        mx2 = fmaxf(mx2, __shfl_xor_sync(0xffffffffu, mx2, o));
    }
    float bmn[3] = { mn0, mn1, mn2 };
    float bmx[3] = { mx0, mx1, mx2 };

    // cov chain applied (v+1) times (fp32, reference op order; reciprocal-mul)
    float C00 = cov[n*9+0], C01 = cov[n*9+1], C02 = cov[n*9+2];
    float C10 = cov[n*9+3], C11 = cov[n*9+4], C12 = cov[n*9+5];
    float C20 = cov[n*9+6], C21 = cov[n*9+7], C22 = cov[n*9+8];
    for (int it = 0; it <= v; it++) {
        float t;
        t = 0.5f*(C01 + C10); C01 = t; C10 = t;
        t = 0.5f*(C02 + C20); C02 = t; C20 = t;
        t = 0.5f*(C12 + C21); C12 = t; C21 = t;
        C00 += 1e-6f; C11 += 1e-6f; C22 += 1e-6f;
        float nrm = sqrtf(C00*C00 + C01*C01 + C02*C02 +
                          C10*C10 + C11*C11 + C12*C12 +
                          C20*C20 + C21*C21 + C22*C22);
        float rden = 1.0f / (nrm + 1e-6f);
        C00 *= rden; C01 *= rden; C02 *= rden;
        C10 *= rden; C11 *= rden; C12 *= rden;
        C20 *= rden; C21 *= rden; C22 *= rden;
    }

    // f64 symmetric 3x3 inverse
    double d00 = C00, d01 = C01, d02 = C02, d11 = C11, d12 = C12, d22 = C22;
    double m00 = d11*d22 - d12*d12;
    double m01 = d02*d12 - d01*d22;
    double m02 = d01*d12 - d02*d11;
    double m11 = d00*d22 - d02*d02;
    double m12 = d01*d02 - d00*d12;
    double m22 = d00*d11 - d01*d01;
    double det = d00*m00 + d01*m01 + d02*m02;
    double idet = 1.0 / det;

    const int A0[3] = {0, 0, 2};
    const int A1[3] = {1, 2, 1};
    const int a0 = A0[v], a1 = A1[v];
    double cof[3][3] = {{m00,m01,m02},{m01,m11,m12},{m02,m12,m22}};
    float a  = (float)(cof[a0][a0]*idet) + 1e-10f;
    float b2 = 2.0f * (float)(cof[a0][a1]*idet);
    float c  = (float)(cof[a1][a1]*idet) + 1e-10f;

    // affine map to [0,111] screen coords (replicating reference fp ops)
    float mnx = bmn[a0], mxx = bmx[a0];
    float mny = bmn[a1], mxy = bmx[a1];
    float rx  = (mxx - mnx) + 1e-6f;
    float m2x = mnx - 0.5f*rx;
    float x2x = mxx + 0.5f*rx;
    float r2x = (x2x - m2x) + 1e-6f;
    float ry  = (mxy - mny) + 1e-6f;
    float m2y = mny - 0.5f*ry;
    float x2y = mxy + 0.5f*ry;
    float r2y = (x2y - m2y) + 1e-6f;
    float Pa  = pos[n*3 + a0];
    float Pb  = pos[n*3 + a1];
    float px = fminf(fmaxf((Pa - m2x) / r2x * 111.0f, 0.0f), 111.0f);
    float py = fminf(fmaxf((Pb - m2y) / r2y * 111.0f, 0.0f), 111.0f);

    float w0 = opa[n] * fminf(fmaxf(imp[n], 0.5f), 2.0f);

    float Af = -L2E * a;
    float Bf = -L2E * b2;
    float Cf = -L2E * c;
    float F0 = 0.1875f * (Af + Cf);

    float bh  = 0.5f * b2;
    float lam = 0.5f*(a + c) - sqrtf(0.25f*(a - c)*(a - c) + bh*bh);
    float rsat2;
    if (lam > 1e-8f) {
        float rs = sqrtf(20.0f / lam) + 0.3536f;
        rsat2 = rs * rs;
    } else {
        rsat2 = 3.0e38f;
    }

    float* dst = &g_par[(v*NG + n)*8];
    dst[0] = px; dst[1] = py; dst[2] = Af; dst[3] = Bf;
    dst[4] = Cf; dst[5] = w0; dst[6] = F0; dst[7] = rsat2;
}

// ---------------------------------------------------------------------------
// Exact-eval inner loop (templated on EDGE pixel handling and disc MASK test).
// (identical to R14)
// ---------------------------------------------------------------------------
template<bool EDGE, bool MASKED>
__device__ __forceinline__ void eval_list(
    const float* __restrict__ sp, int i0, int i1,
    float sx, float vx, float syA, float vyA, float syB, float vyB,
    float hx, float hyA, float hyB,
    float& SA, float& mxA, float& mnA,
    float& SB, float& mxB, float& mnB, bool& skipped)
{
    #pragma unroll 2
    for (int i = i0; i < i1; i++) {
        float4 q0 = *(const float4*)(sp + i*8);      // px,py,A,B
        float4 q1 = *(const float4*)(sp + i*8 + 4);  // C,w0,F0,rsat2
        bool mA = true, mB = true;
        if (MASKED) {
            float dxh  = hx - q0.x;
            float dxh2 = dxh * dxh;
            float dyhA = hyA - q0.y;
            float dyhB = hyB - q0.y;
            mA = dyhA*dyhA + dxh2 < 400.0f;
            mB = dyhB*dyhB + dxh2 < 400.0f;
            if (!__any_sync(0xffffffffu, mA | mB)) { skipped = true; continue; }
        }
        float dx  = sx - q0.x;
        float bdx = q0.w * dx;
        float base;
        if (EDGE) base = q0.z * fmaf(dx, dx, vx);
        else      base = fmaf(q0.z, dx*dx, q1.z);
        {
            float dy = syA - q0.y;
            float u;
            if (EDGE) u = fmaf(q1.x, fmaf(dy, dy, vyA), fmaf(bdx, dy, base));
            else      u = fmaf(q1.x, dy*dy, fmaf(bdx, dy, base));
            u = fmaxf(fminf(u, 0.0f), UMIN);
            float w = mA ? q1.y * ex2f(u) : 0.0f;
            SA += w; mxA = fmaxf(mxA, w); mnA = fminf(mnA, w);
        }
        {
            float dy = syB - q0.y;
            float u;
            if (EDGE) u = fmaf(q1.x, fmaf(dy, dy, vyB), fmaf(bdx, dy, base));
            else      u = fmaf(q1.x, dy*dy, fmaf(bdx, dy, base));
            u = fmaxf(fminf(u, 0.0f), UMIN);
            float w = mB ? q1.y * ex2f(u) : 0.0f;
            SB += w; mxB = fmaxf(mxB, w); mnB = fminf(mnB, w);
        }
    }
}

// ---------------------------------------------------------------------------
// Splat: 16x16 pixel tile, 128 threads, 2 pixels/thread (rows y, y+8).
// R14 structure; the C list (saturated, disc-boundary) is now aggregated on
// the 8x8 HALF-RES grid (contributions are constant per half-pixel): list is
// split across the two thread-halves and combined in smem -> ~4x less C work.
// ---------------------------------------------------------------------------
__global__ __launch_bounds__(128) void splat_kernel()
{
    const int v    = blockIdx.y;
    const int tile = (blockIdx.x * 15) % 196;    // wave-balance permutation
    const int fx0  = (tile % 14) * 16, fy0 = (tile / 14) * 16;
    const int t    = threadIdx.x;
    const int lane = t & 31, wid = t >> 5;
    const int fx   = fx0 + (t & 15);
    const int fyA  = fy0 + (t >> 4);
    const int fyB  = fyA + 8;

    float sx, vx;
    if (fx == 0)        { sx = 0.0f;   vx = 0.0f; }
    else if (fx == 223) { sx = 111.0f; vx = 0.0f; }
    else                { sx = (float)fx * 0.5f - 0.25f; vx = 0.1875f; }
    float syA, vyA;
    if (fyA == 0)        { syA = 0.0f;   vyA = 0.0f; }
    else                 { syA = (float)fyA * 0.5f - 0.25f; vyA = 0.1875f; }
    float syB, vyB;
    if (fyB == 223)      { syB = 111.0f; vyB = 0.0f; }
    else                 { syB = (float)fyB * 0.5f - 0.25f; vyB = 0.1875f; }

    const float hx  = (float)(fx  >> 1);
    const float hyA = (float)(fyA >> 1);
    const float hyB = (float)(fyB >> 1);

    const float rx0 = (float)(fx0 >> 1), rx1 = (float)((fx0 + 15) >> 1);
    const float ry0 = (float)(fy0 >> 1), ry1 = (float)((fy0 + 15) >> 1);

    __shared__ float spA[NG * 8];
    __shared__ float spC[NG * 4];
    __shared__ int   cFA[4], cPA[4], cC[4], cB[4];
    __shared__ float rSum[4], rMin[4], rMax[4];
    __shared__ int   s_front, s_back, s_c, s_nB;
    __shared__ float s_sumB, s_minB, s_maxB;
    // half-res C aggregation
    __shared__ float stS[128], stMn[128], stMx[128];
    __shared__ int   stOut[128];
    __shared__ float sSc[64], sMnC[64], sMxC[64];
    __shared__ int   sOutC[64];
    if (t == 0) {
        s_front = 0; s_back = NG; s_c = 0; s_nB = 0;
        s_sumB = 0.0f; s_minB = 1e30f; s_maxB = -1e30f;
    }
    __syncthreads();

    const float* par = g_par + v * NG * 8;
    const unsigned ltm = (1u << lane) - 1u;

    for (int base = 0; base < NG; base += 128) {
        const int n = base + t;
        float4 q0 = *(const float4*)(par + n*8);
        float4 q1 = *(const float4*)(par + n*8 + 4);
        float px = q0.x, py = q0.y;
        float nx = fminf(fmaxf(px, rx0), rx1) - px;
        float ny = fminf(fmaxf(py, ry0), ry1) - py;
        float dnear2 = nx*nx + ny*ny;
        float fxd = fmaxf(px - rx0, rx1 - px);
        float fyd = fmaxf(py - ry0, ry1 - py);
        float dfar2 = fxd*fxd + fyd*fyd;

        bool keep   = dnear2 < 400.0f;
        bool inside = dfar2  < 400.0f;
        bool sat    = keep && (dnear2 >= q1.w);
        bool bBall  = sat && inside;
        bool bCc    = sat && !inside;
        bool bFA    = keep && !sat && inside;
        bool bPA    = keep && !sat && !inside;

        unsigned mFA = __ballot_sync(0xffffffffu, bFA);
        unsigned mPA = __ballot_sync(0xffffffffu, bPA);
        unsigned mCc = __ballot_sync(0xffffffffu, bCc);
        unsigned mBB = __ballot_sync(0xffffffffu, bBall);

        // warp-reduce B scalars
        float sv  = bBall ? q1.y : 0.0f;
        float mnv = bBall ? q1.y : 1e30f;
        float mxv = bBall ? q1.y : -1e30f;
        #pragma unroll
        for (int o = 16; o > 0; o >>= 1) {
            sv  += __shfl_xor_sync(0xffffffffu, sv,  o);
            mnv  = fminf(mnv, __shfl_xor_sync(0xffffffffu, mnv, o));
            mxv  = fmaxf(mxv, __shfl_xor_sync(0xffffffffu, mxv, o));
        }
        if (lane == 0) {
            cFA[wid] = __popc(mFA); cPA[wid] = __popc(mPA);
            cC[wid]  = __popc(mCc); cB[wid]  = __popc(mBB);
            rSum[wid] = sv; rMin[wid] = mnv; rMax[wid] = mxv;
        }
        __syncthreads();

        int offF = s_front, offP = 0, offC = s_c;
        int totF = 0, totP = 0;
        #pragma unroll
        for (int w = 0; w < 4; w++) {
            if (w < wid) { offF += cFA[w]; offP += cPA[w]; offC += cC[w]; }
            totF += cFA[w]; totP += cPA[w];
        }
        int basePslot = s_back - totP;
        if (bFA | bPA) {
            int slot = bFA ? (offF + __popc(mFA & ltm))
                           : (basePslot + offP + __popc(mPA & ltm));
            *(float4*)(spA + slot*8)     = q0;
            *(float4*)(spA + slot*8 + 4) = q1;
        }
        if (bCc) {
            int slot = offC + __popc(mCc & ltm);
            *(float4*)(spC + slot*4) = make_float4(px, py, EKF * q1.y, 0.0f);
        }
        __syncthreads();
        if (t == 0) {
            int tF = 0, tP = 0, tC = 0, tB = 0;
            float aS = 0.0f, aMn = 1e30f, aMx = -1e30f;
            #pragma unroll
            for (int w = 0; w < 4; w++) {
                tF += cFA[w]; tP += cPA[w]; tC += cC[w]; tB += cB[w];
                aS += rSum[w]; aMn = fminf(aMn, rMin[w]); aMx = fmaxf(aMx, rMax[w]);
            }
            s_front += tF; s_back -= tP; s_c += tC; s_nB += tB;
            s_sumB += aS;
            s_minB = fminf(s_minB, aMn);
            s_maxB = fmaxf(s_maxB, aMx);
        }
        __syncthreads();
    }
    const int nfull = s_front, pstart = s_back, nC = s_c, nB = s_nB;
    const float sumB = s_sumB, minB = s_minB, maxB = s_maxB;

    // ---- C list aggregated at half-res: 64 half-px, list split in halves ----
    {
        const int h    = t & 63;
        const int half = t >> 6;
        const float hxh = rx0 + (float)(h & 7);
        const float hyh = ry0 + (float)(h >> 3);
        float acc = 0.0f, mnc = 1e30f, mxc = -1e30f;
        int   outc = 0;
        for (int i = half; i < nC; i += 2) {
            float4 q = *(const float4*)(spC + i*4);   // px,py,EKF*w0
            float dxh = hxh - q.x;
            float dyh = hyh - q.y;
            bool m = fmaf(dyh, dyh, dxh*dxh) < 400.0f;
            if (m) { acc += q.z; mnc = fminf(mnc, q.z); mxc = fmaxf(mxc, q.z); }
            else   outc = 1;
        }
        stS[t] = acc; stMn[t] = mnc; stMx[t] = mxc; stOut[t] = outc;
    }
    __syncthreads();
    if (t < 64) {
        sSc[t]   = stS[t] + stS[t+64];
        sMnC[t]  = fminf(stMn[t], stMn[t+64]);
        sMxC[t]  = fmaxf(stMx[t], stMx[t+64]);
        sOutC[t] = stOut[t] | stOut[t+64];
    }
    __syncthreads();

    float SA = 0.0f, mxA = -1e30f, mnA = 1e30f;
    float SB = 0.0f, mxB = -1e30f, mnB = 1e30f;
    bool skipped = false;

    const bool interior = (fx0 != 0) && (fx0 != 208) && (fy0 != 0) && (fy0 != 208);
    if (interior) {
        eval_list<false,false>(spA, 0, nfull, sx, vx, syA, vyA, syB, vyB,
                               hx, hyA, hyB, SA, mxA, mnA, SB, mxB, mnB, skipped);
        eval_list<false,true >(spA, pstart, NG, sx, vx, syA, vyA, syB, vyB,
                               hx, hyA, hyB, SA, mxA, mnA, SB, mxB, mnB, skipped);
    } else {
        eval_list<true,false>(spA, 0, nfull, sx, vx, syA, vyA, syB, vyB,
                              hx, hyA, hyB, SA, mxA, mnA, SB, mxB, mnB, skipped);
        eval_list<true,true >(spA, pstart, NG, sx, vx, syA, vyA, syB, vyB,
                              hx, hyA, hyB, SA, mxA, mnA, SB, mxB, mnB, skipped);
    }

    // ---- apply half-res C aggregates to this thread's two pixels ----
    {
        const int hA = (((t >> 4) >> 1) << 3) + ((t & 15) >> 1);
        const int hB = hA + 32;
        SA += sSc[hA];
        mnA = fminf(mnA, sMnC[hA]); mxA = fmaxf(mxA, sMxC[hA]);
        if (sOutC[hA]) { mnA = fminf(mnA, 0.0f); mxA = fmaxf(mxA, 0.0f); }
        SB += sSc[hB];
        mnB = fminf(mnB, sMnC[hB]); mxB = fmaxf(mxB, sMxC[hB]);
        if (sOutC[hB]) { mnB = fminf(mnB, 0.0f); mxB = fmaxf(mxB, 0.0f); }
    }

    // B scalars: identical contribution to every tile pixel
    if (nB > 0) {
        float add = EKF * sumB;
        SA += add; SB += add;
        float bmnv = EKF * minB, bmxv = EKF * maxB;
        mnA = fminf(mnA, bmnv); mxA = fmaxf(mxA, bmxv);
        mnB = fminf(mnB, bmnv); mxB = fmaxf(mxB, bmxv);
    }

    // culled / skipped gaussians contribute exactly zero
    int listed = nfull + (NG - pstart) + nC + nB;
    if (skipped || listed < NG) {
        mnA = fminf(mnA, 0.0f); mxA = fmaxf(mxA, 0.0f);
        mnB = fminf(mnB, 0.0f); mxB = fmaxf(mxB, 0.0f);
    }

    float dmA = 0.5f*(SA - 512.0f*mnA)/((mxA - mnA) + 1e-6f) + SA/(SA + 1e-6f);
    float dmB = 0.5f*(SB - 512.0f*mnB)/((mxB - mnB) + 1e-6f) + SB/(SB + 1e-6f);
    g_d[v*VPIX + fyA*IMGW + fx] = dmA;
    g_d[v*VPIX + fyB*IMGW + fx] = dmB;
}

// ---------------------------------------------------------------------------
// Fully fused fill (both steps) + stats.  (same as R14)
// ---------------------------------------------------------------------------
__device__ __forceinline__ void blur_weights(float& K0, float& K1, float& K2, float& K3)
{
    const double E1 = 0.60653065971263342;
    const double E2 = 0.13533528323661270;
    const double E3 = 0.011108996538242306;
    const double KS = 1.0 + 2.0*(E1 + E2 + E3);
    K0 = (float)(1.0/KS); K1 = (float)(E1/KS); K2 = (float)(E2/KS); K3 = (float)(E3/KS);
}

__global__ __launch_bounds__(256) void fill2_kernel()
{
    const int v  = blockIdx.y;
    const int r0 = blockIdx.x * 8;
    const int t  = threadIdx.x;

    float K0,K1,K2,K3; blur_weights(K0,K1,K2,K3);

    __shared__ float sA[20 * 224];
    __shared__ float sB[14 * 224];
    __shared__ float sC[14 * 224];

    for (int idx = t; idx < 20*224; idx += 256) {
        int row = idx / 224;
        int x   = idx - row * 224;
        int y   = r0 - 6 + row;
        sA[idx] = (y >= 0 && y < 224) ? g_d[v*VPIX + y*224 + x] : 0.0f;
    }
    __syncthreads();

    for (int idx = t; idx < 14*224; idx += 256) {
        sB[idx] = K0 *  sA[idx + 3*224]
                + K1 * (sA[idx + 2*224] + sA[idx + 4*224])
                + K2 * (sA[idx + 1*224] + sA[idx + 5*224])
                + K3 * (sA[idx]          + sA[idx + 6*224]);
    }
    __syncthreads();

    for (int idx = t; idx < 14*224; idx += 256) {
        int j = idx / 224;
        int x = idx - j * 224;
        int yabs = r0 - 3 + j;
        float acc = K0 * sB[idx];
        if (x >= 1)   acc += K1 * sB[idx - 1];
        if (x >= 2)   acc += K2 * sB[idx - 2];
        if (x >= 3)   acc += K3 * sB[idx - 3];
        if (x <= 222) acc += K1 * sB[idx + 1];
        if (x <= 221) acc += K2 * sB[idx + 2];
        if (x <= 220) acc += K3 * sB[idx + 3];
        float dv = sA[idx + 3*224];
        float res = (dv > 1e-6f) ? dv : acc;
        sC[idx] = (yabs >= 0 && yabs < 224) ? res : 0.0f;
    }
    __syncthreads();

    for (int idx = t; idx < 8*224; idx += 256) {
        sB[idx] = K0 *  sC[idx + 3*224]
                + K1 * (sC[idx + 2*224] + sC[idx + 4*224])
                + K2 * (sC[idx + 1*224] + sC[idx + 5*224])
                + K3 * (sC[idx]          + sC[idx + 6*224]);
    }
    __syncthreads();

    double s1 = 0.0, s2 = 0.0;
    for (int idx = t; idx < 8*224; idx += 256) {
        int j = idx / 224;
        int x = idx - j * 224;
        float acc = K0 * sB[idx];
        if (x >= 1)   acc += K1 * sB[idx - 1];
        if (x >= 2)   acc += K2 * sB[idx - 2];
        if (x >= 3)   acc += K3 * sB[idx - 3];
        if (x <= 222) acc += K1 * sB[idx + 1];
        if (x <= 221) acc += K2 * sB[idx + 2];
        if (x <= 220) acc += K3 * sB[idx + 3];
        float dv  = sC[idx + 3*224];
        float res = (dv > 1e-6f) ? dv : acc;
        g_t[v*VPIX + (r0 + j)*224 + x] = res;
        s1 += (double)res; s2 += (double)res * (double)res;
    }

    #pragma unroll
    for (int o = 16; o > 0; o >>= 1) {
        s1 += __shfl_down_sync(0xffffffffu, s1, o);
        s2 += __shfl_down_sync(0xffffffffu, s2, o);
    }
    __shared__ double ws[8], ws2[8];
    int lane = t & 31, wid = t >> 5;
    if (lane == 0) { ws[wid] = s1; ws2[wid] = s2; }
    __syncthreads();
    if (t == 0) {
        double a = 0.0, b = 0.0;
        for (int w = 0; w < 8; w++) { a += ws[w]; b += ws2[w]; }
        atomicAdd(&g_acc[0], a);
        atomicAdd(&g_acc[1], b);
    }
}

// ---------------------------------------------------------------------------
// Normalize: f64 mean/std once per block; float4 vectorized stream.
// NPIX = 150528 = 147 * 256 * 4 exactly.
// ---------------------------------------------------------------------------
__global__ __launch_bounds__(256) void norm_kernel(float* __restrict__ out)
{
    __shared__ float sBias, sScale;
    if (threadIdx.x == 0) {
        double s1 = g_acc[0], s2 = g_acc[1];
        double mean = s1 / (double)NPIX;
        double var  = (s2 - s1*mean) / (double)(NPIX - 1);
        double stdd = sqrt(fmax(var, 0.0));
        sBias  = (float)mean;
        sScale = (float)(1.0 / (stdd + 1e-6));
    }
    __syncthreads();
    int i = blockIdx.x*256 + threadIdx.x;
    float4 x = ((const float4*)g_t)[i];
    float b = sBias, s = sScale;
    float4 y;
    y.x = (x.x - b) * s;
    y.y = (x.y - b) * s;
    y.z = (x.z - b) * s;
    y.w = (x.w - b) * s;
    ((float4*)out)[i] = y;
}

// ---------------------------------------------------------------------------
extern "C" void kernel_launch(void* const* d_in, const int* in_sizes, int n_in,
                              void* d_out, int out_size)
{
    const float* pos = (const float*)d_in[0];  // (1,512,3)
    const float* cov = (const float*)d_in[1];  // (1,512,3,3)
    const float* opa = (const float*)d_in[2];  // (1,512)
    const float* imp = (const float*)d_in[3];  // (1,1000)

    prep_kernel<<<48, 32>>>(pos, cov, opa, imp);
    splat_kernel<<<dim3(196, 3), 128>>>();
    fill2_kernel<<<dim3(28, 3), 256>>>();
    norm_kernel<<<NPIX/1024, 256>>>((float*)d_out);
}